// round 2
// baseline (speedup 1.0000x reference)
#include <cuda_runtime.h>

#define D 64
#define NMAX 150016          // max total nodes (100000 + 50000, padded)
#define RPB 64               // rows per block in fused kernel
#define TPB 512              // threads per block in fused kernel (16 warps)

// Scratch: static device globals (module-load allocation, allowed by harness rules)
__device__ float g_E[NMAX * D];     // current layer embeddings (unnormalized)
__device__ float g_agg[NMAX * D];   // edge aggregation accumulator

__device__ __forceinline__ float lrelu(float x) {
    return x > 0.0f ? x : 0.01f * x;
}

// E0 = concat(user, item); also write raw E0 into out[:, 0:64]
__global__ void init_kernel(const float* __restrict__ user, const float* __restrict__ item,
                            float* __restrict__ out, int n_user, int n_total) {
    int t = blockIdx.x * blockDim.x + threadIdx.x;
    if (t >= n_total * (D / 4)) return;
    int row = t >> 4;
    int c = (t & 15) * 4;
    float4 v;
    if (row < n_user) v = *(const float4*)&user[row * D + c];
    else              v = *(const float4*)&item[(row - n_user) * D + c];
    *(float4*)&g_E[row * D + c] = v;
    *(float4*)&out[row * 4 * D + c] = v;
}

__global__ void zero_kernel(int n_total) {
    int t = blockIdx.x * blockDim.x + threadIdx.x;
    if (t < n_total * (D / 4))
        ((float4*)g_agg)[t] = make_float4(0.f, 0.f, 0.f, 0.f);
}

// agg[row] += val * E[col]  for each edge. 16 threads per edge (one float4 each).
__global__ void scatter_kernel(const int* __restrict__ erow, const int* __restrict__ ecol,
                               const float* __restrict__ eval, int nE) {
    int t = blockIdx.x * blockDim.x + threadIdx.x;
    int e = t >> 4;
    if (e >= nE) return;
    int c = (t & 15) * 4;
    int r  = erow[e];
    int cl = ecol[e];
    float v = eval[e];
    float4 x = *(const float4*)&g_E[cl * D + c];
    float4 m = make_float4(v * x.x, v * x.y, v * x.z, v * x.w);
    atomicAdd((float4*)&g_agg[r * D + c], m);   // vectorized RED (sm_90+)
}

// Per row n:
//   f  = agg[n] + E[n]                 (the +I term folded in here)
//   t  = lrelu(f @ Wf^T + bf)
//   u  = lrelu((E[n]*f) @ Wb^T + bb)
//   Enew = t + u  -> g_E[n] (in place), out[n, col_off:col_off+64] = Enew/||Enew||
// Block: 64 rows, 512 threads. Warp w handles rows 4w..4w+3, lane handles cols (lane, lane+32).
__global__ void fused_kernel(const float* __restrict__ Wf, const float* __restrict__ bfv,
                             const float* __restrict__ Wb, const float* __restrict__ bbv,
                             float* __restrict__ out, int out_col, int n_total) {
    extern __shared__ float sm[];
    float* Wfs = sm;               // [j][k] padded to 68 -> conflict-free float4 reads along k
    float* Wbs = Wfs + 64 * 68;
    float* fs  = Wbs + 64 * 68;    // [k][r] padded to 68 -> one broadcast LDS.128 per 4 rows
    float* efs = fs + 64 * 68;

    int tid  = threadIdx.x;
    int lane = tid & 31;
    int w    = tid >> 5;           // 0..15
    int base = blockIdx.x * RPB;

    // Stage weights (global [j][k] row-major; out[n,j] = sum_k x[n,k]*W[j,k])
    for (int idx = tid; idx < 4096; idx += TPB) {
        int j = idx >> 6, k = idx & 63;
        Wfs[j * 68 + k] = Wf[idx];
        Wbs[j * 68 + k] = Wb[idx];
    }
    // Stage rows: f = agg+E, ef = E*f
    for (int idx = tid; idx < 4096; idx += TPB) {
        int r = idx >> 6, k = idx & 63;
        int row = base + r;
        float e = 0.f, a = 0.f;
        if (row < n_total) {
            e = g_E[row * D + k];
            a = g_agg[row * D + k];
        }
        float f = a + e;
        fs[k * 68 + r]  = f;
        efs[k * 68 + r] = e * f;
    }
    __syncthreads();

    int j0 = lane, j1 = lane + 32;
    int r0 = w * 4;
    float af[4][2], ab[4][2];
    {
        float bf0 = bfv[j0], bf1 = bfv[j1], bb0 = bbv[j0], bb1 = bbv[j1];
        #pragma unroll
        for (int r = 0; r < 4; r++) {
            af[r][0] = bf0; af[r][1] = bf1;
            ab[r][0] = bb0; ab[r][1] = bb1;
        }
    }

    #pragma unroll
    for (int k = 0; k < 64; k += 4) {
        float4 wf0 = *(float4*)&Wfs[j0 * 68 + k];
        float4 wf1 = *(float4*)&Wfs[j1 * 68 + k];
        float4 wb0 = *(float4*)&Wbs[j0 * 68 + k];
        float4 wb1 = *(float4*)&Wbs[j1 * 68 + k];
        #pragma unroll
        for (int kk = 0; kk < 4; kk++) {
            float4 f  = *(float4*)&fs[(k + kk) * 68 + r0];
            float4 ef = *(float4*)&efs[(k + kk) * 68 + r0];
            float a = (&wf0.x)[kk], b = (&wf1.x)[kk];
            float c = (&wb0.x)[kk], d = (&wb1.x)[kk];
            af[0][0] += f.x * a;  af[0][1] += f.x * b;
            af[1][0] += f.y * a;  af[1][1] += f.y * b;
            af[2][0] += f.z * a;  af[2][1] += f.z * b;
            af[3][0] += f.w * a;  af[3][1] += f.w * b;
            ab[0][0] += ef.x * c; ab[0][1] += ef.x * d;
            ab[1][0] += ef.y * c; ab[1][1] += ef.y * d;
            ab[2][0] += ef.z * c; ab[2][1] += ef.z * d;
            ab[3][0] += ef.w * c; ab[3][1] += ef.w * d;
        }
    }

    // Epilogue: leaky-relu, sum, row-norm (warp covers all 64 cols of each of its 4 rows)
    #pragma unroll
    for (int r = 0; r < 4; r++) {
        int row = base + r0 + r;
        float e0 = lrelu(af[r][0]) + lrelu(ab[r][0]);
        float e1 = lrelu(af[r][1]) + lrelu(ab[r][1]);
        float s = e0 * e0 + e1 * e1;
        #pragma unroll
        for (int o = 16; o; o >>= 1) s += __shfl_xor_sync(0xffffffffu, s, o);
        float nrm = fmaxf(sqrtf(s), 1e-12f);
        float inv = 1.0f / nrm;
        if (row < n_total) {
            g_E[row * D + j0] = e0;
            g_E[row * D + j1] = e1;
            out[row * 4 * D + out_col + j0] = e0 * inv;
            out[row * 4 * D + out_col + j1] = e1 * inv;
        }
    }
}

extern "C" void kernel_launch(void* const* d_in, const int* in_sizes, int n_in,
                              void* d_out, int out_size) {
    const float* user = (const float*)d_in[0];
    const float* item = (const float*)d_in[1];
    const int*   erow = (const int*)d_in[2];
    const int*   ecol = (const int*)d_in[3];
    const float* eval = (const float*)d_in[4];
    const float* Wf   = (const float*)d_in[5];
    const float* bf   = (const float*)d_in[6];
    const float* Wb   = (const float*)d_in[7];
    const float* bb   = (const float*)d_in[8];
    float* out = (float*)d_out;

    int n_user = in_sizes[0] / D;
    int n_item = in_sizes[1] / D;
    int N  = n_user + n_item;
    int nE = in_sizes[2];

    const int smem_bytes = 4 * 64 * 68 * 4;  // 69632 B dynamic smem
    cudaFuncSetAttribute(fused_kernel, cudaFuncAttributeMaxDynamicSharedMemorySize, smem_bytes);

    init_kernel<<<(N * 16 + 255) / 256, 256>>>(user, item, out, n_user, N);

    for (int i = 0; i < 3; i++) {
        zero_kernel<<<(N * 16 + 255) / 256, 256>>>(N);
        scatter_kernel<<<(nE * 16 + 255) / 256, 256>>>(erow, ecol, eval, nE);
        fused_kernel<<<(N + RPB - 1) / RPB, TPB, smem_bytes>>>(
            Wf + i * 4096, bf + i * 64, Wb + i * 4096, bb + i * 64,
            out, (i + 1) * 64, N);
    }
}